// round 13
// baseline (speedup 1.0000x reference)
#include <cuda_runtime.h>
#include <cstdint>

// ---------------------------------------------------------------------------
// Problem constants
//   SHAPE = (4, 8, 8, 4), I_CH=32, O_CH=128, BATCH=64, RANK=32
//   core0: (32, 64, 1, 4, 32)   strides (floats): i 8192, b 128, m 32, j 1
//   core1: (32, 64, 32, 8, 32)  strides: i 524288, b 8192, k 256, m 32, j 1
//   core2: same as core1
//   core3: (32, 64, 32, 4, 1)   strides: i 8192, b 128, k 4, m 1
//   weight:(32, 24, 128)        strides: i 3072, row 128, o 1
// ---------------------------------------------------------------------------

static const size_t Y0_OFF = 0;
static const size_t Y1_OFF = 1048576;
static const size_t Y2_OFF = 1048576 + 67108864ull;
static const size_t Y3_OFF = 1048576 + 2ull * 67108864ull;

// ---------------------------------------------------------------------------
// y0: out0[o,b,m,j] = sum_i W[i, m, o] * core0[i,b,0,m,j]
// ---------------------------------------------------------------------------
__global__ void __launch_bounds__(256) y0_kernel(
    const float* __restrict__ core0, const float* __restrict__ weight,
    float* __restrict__ out)
{
    __shared__ float cs[32 * 32];     // [i][j]
    __shared__ float Ws[32 * 128];    // [i][o]
    const int bm = blockIdx.x;
    const int b = bm >> 2;
    const int m = bm & 3;
    const int tid = threadIdx.x;

    {
        int i = tid >> 3, j4 = tid & 7;
        float4 v = *reinterpret_cast<const float4*>(
            core0 + (size_t)i * 8192 + b * 128 + m * 32 + j4 * 4);
        *reinterpret_cast<float4*>(&cs[i * 32 + j4 * 4]) = v;
    }
    #pragma unroll
    for (int q = 0; q < 4; ++q) {
        int idx = tid + 256 * q;
        int i = idx >> 5, o4 = idx & 31;
        float4 v = *reinterpret_cast<const float4*>(
            weight + (size_t)i * 3072 + m * 128 + o4 * 4);
        *reinterpret_cast<float4*>(&Ws[i * 128 + o4 * 4]) = v;
    }
    __syncthreads();

    const int j = tid & 31;
    const int obase = (tid >> 5) * 16;
    float acc[16];
    #pragma unroll
    for (int t = 0; t < 16; ++t) acc[t] = 0.f;
    #pragma unroll 4
    for (int i = 0; i < 32; ++i) {
        float v = cs[i * 32 + j];
        #pragma unroll
        for (int oo = 0; oo < 16; ++oo)
            acc[oo] = fmaf(Ws[i * 128 + obase + oo], v, acc[oo]);
    }
    #pragma unroll
    for (int oo = 0; oo < 16; ++oo)
        out[(size_t)(obase + oo) * 8192 + b * 128 + m * 32 + j] = acc[oo];
}

// ---------------------------------------------------------------------------
// y3: out3[o,b,k,m] = sum_i W[i, 20+m, o] * core3[i,b,k,m]
// ---------------------------------------------------------------------------
__global__ void __launch_bounds__(256) y3_kernel(
    const float* __restrict__ core3, const float* __restrict__ weight,
    float* __restrict__ out)
{
    __shared__ float cs[32 * 128];    // [i][km]
    __shared__ float Ws[32 * 32 * 4]; // [i][o_local][mm]
    const int b = blockIdx.x & 63;
    const int oq = blockIdx.x >> 6;
    const int tid = threadIdx.x;

    #pragma unroll
    for (int q = 0; q < 4; ++q) {
        int idx = tid + 256 * q;
        int i = idx >> 5, km4 = idx & 31;
        float4 v = *reinterpret_cast<const float4*>(
            core3 + (size_t)i * 8192 + b * 128 + km4 * 4);
        *reinterpret_cast<float4*>(&cs[i * 128 + km4 * 4]) = v;
    }
    #pragma unroll
    for (int q = 0; q < 16; ++q) {
        int idx = tid + 256 * q;
        int i = idx >> 7;
        int rem = idx & 127;
        int mm = rem >> 5;
        int ol = rem & 31;
        Ws[(i * 32 + ol) * 4 + mm] =
            weight[(size_t)i * 3072 + (20 + mm) * 128 + oq * 32 + ol];
    }
    __syncthreads();

    const int km = tid & 127;
    const int oh = tid >> 7;
    const int mm = km & 3;
    float acc[16];
    #pragma unroll
    for (int t = 0; t < 16; ++t) acc[t] = 0.f;
    #pragma unroll 4
    for (int i = 0; i < 32; ++i) {
        float v = cs[i * 128 + km];
        #pragma unroll
        for (int oo = 0; oo < 16; ++oo)
            acc[oo] = fmaf(Ws[(i * 32 + oh * 16 + oo) * 4 + mm], v, acc[oo]);
    }
    #pragma unroll
    for (int oo = 0; oo < 16; ++oo) {
        int o = oq * 32 + oh * 16 + oo;
        out[((size_t)o * 64 + b) * 128 + km] = acc[oo];
    }
}

// ---------------------------------------------------------------------------
// cp.async helpers
// ---------------------------------------------------------------------------
__device__ __forceinline__ void cp_async16(float* smem_dst, const float* gmem_src)
{
    uint32_t s = (uint32_t)__cvta_generic_to_shared(smem_dst);
    asm volatile("cp.async.cg.shared.global [%0], [%1], 16;\n"
                 :: "r"(s), "l"(gmem_src) : "memory");
}
__device__ __forceinline__ void cp_async_commit()
{
    asm volatile("cp.async.commit_group;\n" ::: "memory");
}
template<int N>
__device__ __forceinline__ void cp_async_wait()
{
    asm volatile("cp.async.wait_group %0;\n" :: "n"(N) : "memory");
}

// ---------------------------------------------------------------------------
// Fused cores 1 & 2 (single launch, z = core):
//   A[o,k,j] = sum_i 0.5*W[i,off+m,o] * (c[i,b,j,m,k] - c[i,b,k,m,j])   (skew)
//   Q = (I-A)^{-1}(I+A) = 2*(I-A)^{-1} - I
// R13: o-tile = 32 (was 16), 1024 threads / 32 warps per block.
//   Each (b,m,core) core slice is now loaded/antisymmetrized 4x instead of
//   8x: cp.async fill and the triangle LDS (the conflicted scalar reads)
//   amortize over 32 o's -> total L1 wavefronts for phase 1 halve.
//   Phase 2: 32 matrices on 32 warps, one per warp (no serialization).
// Phase 1: cp.async 4-buffer / 3-ahead pipeline over 8 chunks of 4 i;
//   1 op/thread/chunk.
// Phase 2: per-warp blocked register Gauss-Jordan (panel width 8), as R8.
// Epilogue: XOR-swizzled Qstage + coalesced STG.128 (4 lines/warp-store).
// smem eras (floats):  Amat [0,33792) = 32 x [32][33];
//   era1 staging raw [0,18432) and era3 Qstage [0,32768) alias it;
//   Ws at [33792, 34816).  acc[32] (phase1) and M[32] (phase2) are
//   sequentially live -> ~50 regs, no spills at the 64-reg/1024t budget.
// No pivoting needed: sym(I-A)=I  =>  every pivot >= 1.
// ---------------------------------------------------------------------------
__global__ void __launch_bounds__(1024, 1) cayley_kernel(
    const float* __restrict__ core1,
    const float* __restrict__ core2,
    const float* __restrict__ weight,
    float* __restrict__ out)
{
    const int og = blockIdx.x;            // 0..3   (o-group of 32)
    const int bm = blockIdx.y;            // 0..511
    const int b  = bm >> 3;
    const int m  = bm & 7;
    const int c  = blockIdx.z;            // 0..1
    const float* core = c ? core2 : core1;
    float* yout = out + (c ? Y2_OFF : Y1_OFF);
    const int woff = 4 + 8 * c;

    extern __shared__ float smem[];
    float* raw  = smem;                   // era 1: 4 buffers x [4][32][36]
    float* Amat = smem;                   // era 2: 32 x [32][33] = 33792
    float* Ws   = smem + 33792;           // [32 i][32 oo] = 1024, persistent

    const int tid = threadIdx.x;

    {   // 0.5*W slice: Ws[i][oo], one value per thread
        int i  = tid >> 5;
        int oo = tid & 31;
        Ws[i * 32 + oo] =
            0.5f * weight[(size_t)i * 3072 + (woff + m) * 128 + og * 32 + oo];
    }

    // thread -> strict-upper-triangle pair (pk < pj)
    int pk = 0, pj = 0;
    if (tid < 496) {
        int rem = tid, k = 0;
        #pragma unroll 1
        while (rem >= 31 - k) { rem -= 31 - k; ++k; }
        pk = k;
        pj = k + 1 + rem;
    }

    float acc[32];
    #pragma unroll
    for (int oo = 0; oo < 32; ++oo) acc[oo] = 0.f;

    const float* cbase = core + (size_t)b * 8192 + m * 32;

    // per-thread cp.async slot (1 float4 per thread per chunk)
    const int il0 = tid >> 8;             // 0..3
    const int k0  = (tid >> 3) & 31;      // 0..31
    const int j40 = tid & 7;              // 0..7
    const int d0  = (il0 * 32 + k0) * 36 + j40 * 4;
    const size_t g0 = (size_t)il0 * 524288 + k0 * 256 + j40 * 4;

    // --- phase 1: 4-buffer cp.async pipeline, 8 chunks of 4 i --------------
    #pragma unroll
    for (int pre = 0; pre < 3; ++pre) {   // prologue: chunks 0,1,2 in flight
        float* dbuf = raw + pre * 4608;
        const float* src = cbase + (size_t)pre * 4 * 524288;
        cp_async16(dbuf + d0, src + g0);
        cp_async_commit();
    }

    #pragma unroll 1
    for (int ch = 0; ch < 8; ++ch) {
        if      (ch < 6)  cp_async_wait<2>();
        else if (ch == 6) cp_async_wait<1>();
        else              cp_async_wait<0>();
        __syncthreads();                  // chunk ch visible; ch-1 reads done

        if (ch < 5) {                     // issue chunk ch+3 into buffer of ch-1
            float* dbuf = raw + ((ch + 3) & 3) * 4608;
            const float* src = cbase + (size_t)(ch + 3) * 4 * 524288;
            cp_async16(dbuf + d0, src + g0);
            cp_async_commit();
        }

        if (tid < 496) {
            const float* rb = raw + (ch & 3) * 4608;
            #pragma unroll
            for (int il = 0; il < 4; ++il) {
                float dval = rb[(il * 32 + pj) * 36 + pk]
                           - rb[(il * 32 + pk) * 36 + pj];
                const float* wrow = &Ws[(ch * 4 + il) * 32];
                #pragma unroll
                for (int oo = 0; oo < 32; ++oo)
                    acc[oo] = fmaf(wrow[oo], dval, acc[oo]);
            }
        }
    }
    __syncthreads();                      // last chunk reads done; raw dead

    // --- mirror into smem A matrices (Amat aliases raw) ---------------------
    if (tid < 496) {
        #pragma unroll
        for (int oo = 0; oo < 32; ++oo) {
            Amat[oo * 1056 + pk * 33 + pj] = acc[oo];
            Amat[oo * 1056 + pj * 33 + pk] = -acc[oo];
        }
    } else if (tid < 528) {
        int oo = tid - 496;               // 0..31: zero the diagonal
        #pragma unroll
        for (int dd = 0; dd < 32; ++dd)
            Amat[oo * 1056 + dd * 33 + dd] = 0.f;
    }
    __syncthreads();

    // --- phase 2: per-warp blocked Gauss-Jordan inverse of M = I - A --------
    const int w    = tid >> 5;            // warp -> matrix index (0..31)
    const int lane = tid & 31;            // lane -> row index

    float M[32];
    #pragma unroll
    for (int q = 0; q < 32; ++q)
        M[q] = (lane == q ? 1.0f : 0.0f) - Amat[w * 1056 + lane * 33 + q];

    // Warp-private scratch aliased onto this warp's OWN (now dead) Amat slice:
    float* Sw = Amat + w * 1056;
    __syncwarp();                         // M-init loads done before STS alias

    #pragma unroll
    for (int P = 0; P < 4; ++P) {
        const int base = 8 * P;
        float* buf = Sw + (P & 1) * 288;

        // publish pre-panel rows of the 8 panel lanes (all 32 cols)
        if ((lane >> 3) == P) {
            float* row = buf + (lane & 7) * 36;
            #pragma unroll
            for (int g4 = 0; g4 < 8; ++g4)
                *reinterpret_cast<float4*>(row + g4 * 4) =
                    make_float4(M[g4 * 4 + 0], M[g4 * 4 + 1],
                                M[g4 * 4 + 2], M[g4 * 4 + 3]);
        }

        // mini-GJ restricted to panel columns [base, base+8)
        #pragma unroll
        for (int pp = 0; pp < 8; ++pp) {
            const int p = base + pp;
            float piv = __shfl_sync(0xffffffffu, M[p], p);
            float d   = __fdividef(1.0f, piv);   // pivots >= 1, always safe
            float g   = (lane == p) ? (1.0f - d) : M[p] * d;
            #pragma unroll
            for (int qq = 0; qq < 8; ++qq) {
                if (qq == pp) continue;
                const int q = base + qq;
                float prq = __shfl_sync(0xffffffffu, M[q], p);
                M[q] = fmaf(-g, prq, M[q]);
            }
            M[p] = (lane == p) ? d : -g;
        }
        __syncwarp();                     // publish visible; prev buf reads done

        // rank-8 update of the 24 non-panel columns:
        //   M[r][q] = keep * M[r][q] + sum_t E[r][base+t] * S[t][q]
        const float keep = ((lane >> 3) == P) ? 0.0f : 1.0f;
        #pragma unroll
        for (int g4 = 0; g4 < 8; ++g4) {
            if (g4 == 2 * P || g4 == 2 * P + 1) continue;   // compile-time skip
            M[g4 * 4 + 0] *= keep;
            M[g4 * 4 + 1] *= keep;
            M[g4 * 4 + 2] *= keep;
            M[g4 * 4 + 3] *= keep;
        }
        #pragma unroll
        for (int t = 0; t < 8; ++t) {
            const float h = M[base + t];              // E[lane][base+t]
            const float* srow = buf + t * 36;
            #pragma unroll
            for (int g4 = 0; g4 < 8; ++g4) {
                if (g4 == 2 * P || g4 == 2 * P + 1) continue;
                float4 s = *reinterpret_cast<const float4*>(srow + g4 * 4);
                M[g4 * 4 + 0] = fmaf(h, s.x, M[g4 * 4 + 0]);
                M[g4 * 4 + 1] = fmaf(h, s.y, M[g4 * 4 + 1]);
                M[g4 * 4 + 2] = fmaf(h, s.z, M[g4 * 4 + 2]);
                M[g4 * 4 + 3] = fmaf(h, s.w, M[g4 * 4 + 3]);
            }
        }
    }

    // --- epilogue: Q = 2*Minv - I staged to XOR-swizzled smem, then
    //     coalesced STG.128 (each warp-store touches 4 cache lines) ---------
    __syncthreads();                      // all warps done with Amat/Sw
    {
        // Qstage[w][lane][g] : stride 32, group swizzle g = q4 ^ (lane&7)
        float* qrow = smem + w * 1024 + lane * 32;
        const int sw = lane & 7;
        #pragma unroll
        for (int q4 = 0; q4 < 8; ++q4) {
            float4 v;
            v.x = 2.f * M[q4 * 4 + 0] - (lane == q4 * 4 + 0 ? 1.f : 0.f);
            v.y = 2.f * M[q4 * 4 + 1] - (lane == q4 * 4 + 1 ? 1.f : 0.f);
            v.z = 2.f * M[q4 * 4 + 2] - (lane == q4 * 4 + 2 ? 1.f : 0.f);
            v.w = 2.f * M[q4 * 4 + 3] - (lane == q4 * 4 + 3 ? 1.f : 0.f);
            *reinterpret_cast<float4*>(qrow + ((q4 ^ sw) << 2)) = v;
        }
    }
    __syncwarp();                         // warp-private region: syncwarp ok
    {
        const int o = og * 32 + w;
        float* obase = yout + ((size_t)o * 64 + b) * 8192 + m * 32;
        const int krow_lo = lane >> 3;    // 0..3
        const int j4      = lane & 7;     // 0..7
        const float* qbase = smem + w * 1024;
        #pragma unroll
        for (int it = 0; it < 8; ++it) {
            const int krow = it * 4 + krow_lo;
            float4 v = *reinterpret_cast<const float4*>(
                qbase + krow * 32 + (((j4 ^ (krow & 7))) << 2));
            *reinterpret_cast<float4*>(obase + krow * 256 + j4 * 4) = v;
        }
    }
}

// ---------------------------------------------------------------------------
extern "C" void kernel_launch(void* const* d_in, const int* in_sizes, int n_in,
                              void* d_out, int out_size)
{
    (void)in_sizes; (void)n_in; (void)out_size;
    const float* core0  = (const float*)d_in[0];
    const float* core1  = (const float*)d_in[1];
    const float* core2  = (const float*)d_in[2];
    const float* core3  = (const float*)d_in[3];
    const float* weight = (const float*)d_in[4];
    float* out = (float*)d_out;

    static const int SMEM_BYTES = (33792 + 1024) * 4;   // 139264 B
    cudaFuncSetAttribute(cayley_kernel,
                         cudaFuncAttributeMaxDynamicSharedMemorySize,
                         SMEM_BYTES);

    cayley_kernel<<<dim3(4, 512, 2), 1024, SMEM_BYTES>>>(
        core1, core2, weight, out);
    y0_kernel<<<256, 256>>>(core0, weight, out + Y0_OFF);
    y3_kernel<<<256, 256>>>(core3, weight, out + Y3_OFF);
}

// round 14
// speedup vs baseline: 1.0536x; 1.0536x over previous
#include <cuda_runtime.h>
#include <cstdint>

// ---------------------------------------------------------------------------
// Problem constants
//   SHAPE = (4, 8, 8, 4), I_CH=32, O_CH=128, BATCH=64, RANK=32
//   core0: (32, 64, 1, 4, 32)   strides (floats): i 8192, b 128, m 32, j 1
//   core1: (32, 64, 32, 8, 32)  strides: i 524288, b 8192, k 256, m 32, j 1
//   core2: same as core1
//   core3: (32, 64, 32, 4, 1)   strides: i 8192, b 128, k 4, m 1
//   weight:(32, 24, 128)        strides: i 3072, row 128, o 1
// ---------------------------------------------------------------------------

static const size_t Y0_OFF = 0;
static const size_t Y1_OFF = 1048576;
static const size_t Y2_OFF = 1048576 + 67108864ull;
static const size_t Y3_OFF = 1048576 + 2ull * 67108864ull;

// ---------------------------------------------------------------------------
// y0: out0[o,b,m,j] = sum_i W[i, m, o] * core0[i,b,0,m,j]
// ---------------------------------------------------------------------------
__global__ void __launch_bounds__(256) y0_kernel(
    const float* __restrict__ core0, const float* __restrict__ weight,
    float* __restrict__ out)
{
    __shared__ float cs[32 * 32];     // [i][j]
    __shared__ float Ws[32 * 128];    // [i][o]
    const int bm = blockIdx.x;
    const int b = bm >> 2;
    const int m = bm & 3;
    const int tid = threadIdx.x;

    {
        int i = tid >> 3, j4 = tid & 7;
        float4 v = *reinterpret_cast<const float4*>(
            core0 + (size_t)i * 8192 + b * 128 + m * 32 + j4 * 4);
        *reinterpret_cast<float4*>(&cs[i * 32 + j4 * 4]) = v;
    }
    #pragma unroll
    for (int q = 0; q < 4; ++q) {
        int idx = tid + 256 * q;
        int i = idx >> 5, o4 = idx & 31;
        float4 v = *reinterpret_cast<const float4*>(
            weight + (size_t)i * 3072 + m * 128 + o4 * 4);
        *reinterpret_cast<float4*>(&Ws[i * 128 + o4 * 4]) = v;
    }
    __syncthreads();

    const int j = tid & 31;
    const int obase = (tid >> 5) * 16;
    float acc[16];
    #pragma unroll
    for (int t = 0; t < 16; ++t) acc[t] = 0.f;
    #pragma unroll 4
    for (int i = 0; i < 32; ++i) {
        float v = cs[i * 32 + j];
        #pragma unroll
        for (int oo = 0; oo < 16; ++oo)
            acc[oo] = fmaf(Ws[i * 128 + obase + oo], v, acc[oo]);
    }
    #pragma unroll
    for (int oo = 0; oo < 16; ++oo)
        out[(size_t)(obase + oo) * 8192 + b * 128 + m * 32 + j] = acc[oo];
}

// ---------------------------------------------------------------------------
// y3: out3[o,b,k,m] = sum_i W[i, 20+m, o] * core3[i,b,k,m]
// ---------------------------------------------------------------------------
__global__ void __launch_bounds__(256) y3_kernel(
    const float* __restrict__ core3, const float* __restrict__ weight,
    float* __restrict__ out)
{
    __shared__ float cs[32 * 128];    // [i][km]
    __shared__ float Ws[32 * 32 * 4]; // [i][o_local][mm]
    const int b = blockIdx.x & 63;
    const int oq = blockIdx.x >> 6;
    const int tid = threadIdx.x;

    #pragma unroll
    for (int q = 0; q < 4; ++q) {
        int idx = tid + 256 * q;
        int i = idx >> 5, km4 = idx & 31;
        float4 v = *reinterpret_cast<const float4*>(
            core3 + (size_t)i * 8192 + b * 128 + km4 * 4);
        *reinterpret_cast<float4*>(&cs[i * 128 + km4 * 4]) = v;
    }
    #pragma unroll
    for (int q = 0; q < 16; ++q) {
        int idx = tid + 256 * q;
        int i = idx >> 7;
        int rem = idx & 127;
        int mm = rem >> 5;
        int ol = rem & 31;
        Ws[(i * 32 + ol) * 4 + mm] =
            weight[(size_t)i * 3072 + (20 + mm) * 128 + oq * 32 + ol];
    }
    __syncthreads();

    const int km = tid & 127;
    const int oh = tid >> 7;
    const int mm = km & 3;
    float acc[16];
    #pragma unroll
    for (int t = 0; t < 16; ++t) acc[t] = 0.f;
    #pragma unroll 4
    for (int i = 0; i < 32; ++i) {
        float v = cs[i * 128 + km];
        #pragma unroll
        for (int oo = 0; oo < 16; ++oo)
            acc[oo] = fmaf(Ws[(i * 32 + oh * 16 + oo) * 4 + mm], v, acc[oo]);
    }
    #pragma unroll
    for (int oo = 0; oo < 16; ++oo) {
        int o = oq * 32 + oh * 16 + oo;
        out[((size_t)o * 64 + b) * 128 + km] = acc[oo];
    }
}

// ---------------------------------------------------------------------------
// cp.async helpers
// ---------------------------------------------------------------------------
__device__ __forceinline__ void cp_async16(float* smem_dst, const float* gmem_src)
{
    uint32_t s = (uint32_t)__cvta_generic_to_shared(smem_dst);
    asm volatile("cp.async.cg.shared.global [%0], [%1], 16;\n"
                 :: "r"(s), "l"(gmem_src) : "memory");
}
__device__ __forceinline__ void cp_async_commit()
{
    asm volatile("cp.async.commit_group;\n" ::: "memory");
}
template<int N>
__device__ __forceinline__ void cp_async_wait()
{
    asm volatile("cp.async.wait_group %0;\n" :: "n"(N) : "memory");
}

// ---------------------------------------------------------------------------
// Fused cores 1 & 2 (single launch, z = core)  —  R12 structure + R14 fix:
//   A[o,k,j] = sum_i 0.5*W[i,off+m,o] * (c[i,b,j,m,k] - c[i,b,k,m,j])   (skew)
//   Q = (I-A)^{-1}(I+A) = 2*(I-A)^{-1} - I
// R14: phase-1 Ws reads via explicit float4 broadcast LDS.128 (4 per il
//   instead of 16 scalar LDS.32). Same bytes, 4x fewer L1 issue slots /
//   crossbar transactions — the Ws broadcasts were ~50% of the kernel's
//   L1 wavefronts (the measured 80.7% L1 binder).
// Phase 1: cp.async 4-buffer / 3-ahead pipeline over 8 chunks of 4 i.
// Phase 2: per-warp blocked register Gauss-Jordan (panel width 8), as R8.
// Epilogue: XOR-swizzled Qstage + coalesced STG.128.
// Amat aliases the phase-1 staging buffers (never simultaneously live).
// __launch_bounds__(512,2): 64-reg budget, no spills, 2 CTAs/SM.
// No pivoting needed: sym(I-A)=I  =>  every pivot >= 1.
// ---------------------------------------------------------------------------
__global__ void __launch_bounds__(512, 2) cayley_kernel(
    const float* __restrict__ core1,
    const float* __restrict__ core2,
    const float* __restrict__ weight,
    float* __restrict__ out)
{
    const int og = blockIdx.x;            // 0..7   (o-group of 16)
    const int bm = blockIdx.y;            // 0..511
    const int b  = bm >> 3;
    const int m  = bm & 7;
    const int c  = blockIdx.z;            // 0..1
    const float* core = c ? core2 : core1;
    float* yout = out + (c ? Y2_OFF : Y1_OFF);
    const int woff = 4 + 8 * c;

    extern __shared__ float smem[];
    // Era 1 (phase 1): raw = smem[0 .. 18432)  = 4 buffers x [4][32][36]
    // Era 2 (phase 2): Amat = smem[0 .. 16896) = [16][32][33]  (aliases raw)
    // Era 3 (epilogue): Qstage = smem[0 .. 16384) = [16][32][32] XOR-swizzled
    // Always: Ws = smem[18432 .. 18944)
    float* raw  = smem;
    float* Amat = smem;
    float* Ws   = smem + 18432;

    const int tid = threadIdx.x;

    {   // 0.5*W slice
        int i  = tid >> 4;
        int oo = tid & 15;
        Ws[i * 16 + oo] =
            0.5f * weight[(size_t)i * 3072 + (woff + m) * 128 + og * 16 + oo];
    }

    // thread -> strict-upper-triangle pair (pk < pj)
    int pk = 0, pj = 0;
    if (tid < 496) {
        int rem = tid, k = 0;
        #pragma unroll 1
        while (rem >= 31 - k) { rem -= 31 - k; ++k; }
        pk = k;
        pj = k + 1 + rem;
    }

    float acc[16];
    #pragma unroll
    for (int oo = 0; oo < 16; ++oo) acc[oo] = 0.f;

    const float* cbase = core + (size_t)b * 8192 + m * 32;

    // per-thread cp.async slot (2 float4 per thread per chunk)
    const int il0 = tid >> 8;             // 0..1
    const int k0  = (tid >> 3) & 31;      // 0..31
    const int j40 = tid & 7;              // 0..7
    const int il1 = il0 + 2;              // 2..3
    const int d0  = (il0 * 32 + k0) * 36 + j40 * 4;
    const int d1  = (il1 * 32 + k0) * 36 + j40 * 4;
    const size_t g0 = (size_t)il0 * 524288 + k0 * 256 + j40 * 4;
    const size_t g1 = (size_t)il1 * 524288 + k0 * 256 + j40 * 4;

    // --- phase 1: 4-buffer cp.async pipeline, 8 chunks of 4 i --------------
    #pragma unroll
    for (int pre = 0; pre < 3; ++pre) {   // prologue: chunks 0,1,2 in flight
        float* dbuf = raw + pre * 4608;
        const float* src = cbase + (size_t)pre * 4 * 524288;
        cp_async16(dbuf + d0, src + g0);
        cp_async16(dbuf + d1, src + g1);
        cp_async_commit();
    }

    #pragma unroll 1
    for (int ch = 0; ch < 8; ++ch) {
        // wait for chunk ch (keep up to min(2, 7-ch) newer groups in flight)
        if      (ch < 6)  cp_async_wait<2>();
        else if (ch == 6) cp_async_wait<1>();
        else              cp_async_wait<0>();
        __syncthreads();                  // chunk ch visible; ch-1 reads done

        if (ch < 5) {                     // issue chunk ch+3 into buffer of ch-1
            float* dbuf = raw + ((ch + 3) & 3) * 4608;
            const float* src = cbase + (size_t)(ch + 3) * 4 * 524288;
            cp_async16(dbuf + d0, src + g0);
            cp_async16(dbuf + d1, src + g1);
            cp_async_commit();
        }

        if (tid < 496) {
            const float* rb = raw + (ch & 3) * 4608;
            #pragma unroll
            for (int il = 0; il < 4; ++il) {
                float dval = rb[(il * 32 + pj) * 36 + pk]
                           - rb[(il * 32 + pk) * 36 + pj];
                // R14: Ws row via 4 broadcast LDS.128 (was 16 scalar LDS.32)
                const float4* wrow4 = reinterpret_cast<const float4*>(
                    &Ws[(ch * 4 + il) * 16]);
                float4 w0 = wrow4[0];
                float4 w1 = wrow4[1];
                float4 w2 = wrow4[2];
                float4 w3 = wrow4[3];
                acc[ 0] = fmaf(w0.x, dval, acc[ 0]);
                acc[ 1] = fmaf(w0.y, dval, acc[ 1]);
                acc[ 2] = fmaf(w0.z, dval, acc[ 2]);
                acc[ 3] = fmaf(w0.w, dval, acc[ 3]);
                acc[ 4] = fmaf(w1.x, dval, acc[ 4]);
                acc[ 5] = fmaf(w1.y, dval, acc[ 5]);
                acc[ 6] = fmaf(w1.z, dval, acc[ 6]);
                acc[ 7] = fmaf(w1.w, dval, acc[ 7]);
                acc[ 8] = fmaf(w2.x, dval, acc[ 8]);
                acc[ 9] = fmaf(w2.y, dval, acc[ 9]);
                acc[10] = fmaf(w2.z, dval, acc[10]);
                acc[11] = fmaf(w2.w, dval, acc[11]);
                acc[12] = fmaf(w3.x, dval, acc[12]);
                acc[13] = fmaf(w3.y, dval, acc[13]);
                acc[14] = fmaf(w3.z, dval, acc[14]);
                acc[15] = fmaf(w3.w, dval, acc[15]);
            }
        }
    }
    __syncthreads();                      // last chunk reads done; raw dead

    // --- mirror into smem A matrices (Amat aliases raw) ---------------------
    if (tid < 496) {
        #pragma unroll
        for (int oo = 0; oo < 16; ++oo) {
            Amat[(oo * 32 + pk) * 33 + pj] = acc[oo];
            Amat[(oo * 32 + pj) * 33 + pk] = -acc[oo];
        }
    } else {
        int oo = tid - 496;
        #pragma unroll
        for (int dd = 0; dd < 32; ++dd)
            Amat[(oo * 32 + dd) * 33 + dd] = 0.f;
    }
    __syncthreads();

    // --- phase 2: per-warp blocked Gauss-Jordan inverse of M = I - A --------
    const int w    = tid >> 5;            // warp -> matrix index
    const int lane = tid & 31;            // lane -> row index

    float M[32];
    #pragma unroll
    for (int q = 0; q < 32; ++q)
        M[q] = (lane == q ? 1.0f : 0.0f) - Amat[(w * 32 + lane) * 33 + q];

    // Warp-private scratch aliased onto this warp's OWN (now dead) Amat rows:
    float* Sw = Amat + w * 1056;
    __syncwarp();                         // M-init loads done before STS alias

    #pragma unroll
    for (int P = 0; P < 4; ++P) {
        const int base = 8 * P;
        float* buf = Sw + (P & 1) * 288;

        // publish pre-panel rows of the 8 panel lanes (all 32 cols)
        if ((lane >> 3) == P) {
            float* row = buf + (lane & 7) * 36;
            #pragma unroll
            for (int g4 = 0; g4 < 8; ++g4)
                *reinterpret_cast<float4*>(row + g4 * 4) =
                    make_float4(M[g4 * 4 + 0], M[g4 * 4 + 1],
                                M[g4 * 4 + 2], M[g4 * 4 + 3]);
        }

        // mini-GJ restricted to panel columns [base, base+8)
        #pragma unroll
        for (int pp = 0; pp < 8; ++pp) {
            const int p = base + pp;
            float piv = __shfl_sync(0xffffffffu, M[p], p);
            float d   = __fdividef(1.0f, piv);   // pivots >= 1, always safe
            float g   = (lane == p) ? (1.0f - d) : M[p] * d;
            #pragma unroll
            for (int qq = 0; qq < 8; ++qq) {
                if (qq == pp) continue;
                const int q = base + qq;
                float prq = __shfl_sync(0xffffffffu, M[q], p);
                M[q] = fmaf(-g, prq, M[q]);
            }
            M[p] = (lane == p) ? d : -g;
        }
        __syncwarp();                     // publish visible; prev buf reads done

        // rank-8 update of the 24 non-panel columns:
        //   M[r][q] = keep * M[r][q] + sum_t E[r][base+t] * S[t][q]
        const float keep = ((lane >> 3) == P) ? 0.0f : 1.0f;
        #pragma unroll
        for (int g4 = 0; g4 < 8; ++g4) {
            if (g4 == 2 * P || g4 == 2 * P + 1) continue;   // compile-time skip
            M[g4 * 4 + 0] *= keep;
            M[g4 * 4 + 1] *= keep;
            M[g4 * 4 + 2] *= keep;
            M[g4 * 4 + 3] *= keep;
        }
        #pragma unroll
        for (int t = 0; t < 8; ++t) {
            const float h = M[base + t];              // E[lane][base+t]
            const float* srow = buf + t * 36;
            #pragma unroll
            for (int g4 = 0; g4 < 8; ++g4) {
                if (g4 == 2 * P || g4 == 2 * P + 1) continue;
                float4 s = *reinterpret_cast<const float4*>(srow + g4 * 4);
                M[g4 * 4 + 0] = fmaf(h, s.x, M[g4 * 4 + 0]);
                M[g4 * 4 + 1] = fmaf(h, s.y, M[g4 * 4 + 1]);
                M[g4 * 4 + 2] = fmaf(h, s.z, M[g4 * 4 + 2]);
                M[g4 * 4 + 3] = fmaf(h, s.w, M[g4 * 4 + 3]);
            }
        }
    }

    // --- epilogue: Q = 2*Minv - I staged to XOR-swizzled smem, then
    //     coalesced STG.128 (each warp-store touches 4 cache lines) ---------
    __syncthreads();                      // all Sw scratch dead block-wide
    {
        // Qstage[w][lane][g] : stride 32, group swizzle g = q4 ^ (lane&7)
        float* qrow = smem + w * 1024 + lane * 32;
        const int sw = lane & 7;
        #pragma unroll
        for (int q4 = 0; q4 < 8; ++q4) {
            float4 v;
            v.x = 2.f * M[q4 * 4 + 0] - (lane == q4 * 4 + 0 ? 1.f : 0.f);
            v.y = 2.f * M[q4 * 4 + 1] - (lane == q4 * 4 + 1 ? 1.f : 0.f);
            v.z = 2.f * M[q4 * 4 + 2] - (lane == q4 * 4 + 2 ? 1.f : 0.f);
            v.w = 2.f * M[q4 * 4 + 3] - (lane == q4 * 4 + 3 ? 1.f : 0.f);
            *reinterpret_cast<float4*>(qrow + ((q4 ^ sw) << 2)) = v;
        }
    }
    __syncwarp();                         // warp-private region: syncwarp ok
    {
        const int o = og * 16 + w;
        float* obase = yout + ((size_t)o * 64 + b) * 8192 + m * 32;
        const int krow_lo = lane >> 3;    // 0..3
        const int j4      = lane & 7;     // 0..7
        const float* qbase = smem + w * 1024;
        #pragma unroll
        for (int it = 0; it < 8; ++it) {
            const int krow = it * 4 + krow_lo;
            float4 v = *reinterpret_cast<const float4*>(
                qbase + krow * 32 + (((j4 ^ (krow & 7))) << 2));
            *reinterpret_cast<float4*>(obase + krow * 256 + j4 * 4) = v;
        }
    }
}

// ---------------------------------------------------------------------------
extern "C" void kernel_launch(void* const* d_in, const int* in_sizes, int n_in,
                              void* d_out, int out_size)
{
    (void)in_sizes; (void)n_in; (void)out_size;
    const float* core0  = (const float*)d_in[0];
    const float* core1  = (const float*)d_in[1];
    const float* core2  = (const float*)d_in[2];
    const float* core3  = (const float*)d_in[3];
    const float* weight = (const float*)d_in[4];
    float* out = (float*)d_out;

    static const int SMEM_BYTES = 18944 * 4;   // 75776 B
    cudaFuncSetAttribute(cayley_kernel,
                         cudaFuncAttributeMaxDynamicSharedMemorySize,
                         SMEM_BYTES);

    cayley_kernel<<<dim3(8, 512, 2), 512, SMEM_BYTES>>>(
        core1, core2, weight, out);
    y0_kernel<<<256, 256>>>(core0, weight, out + Y0_OFF);
    y3_kernel<<<256, 256>>>(core3, weight, out + Y3_OFF);
}

// round 15
// speedup vs baseline: 1.1590x; 1.1001x over previous
#include <cuda_runtime.h>
#include <cstdint>

// ---------------------------------------------------------------------------
// Problem constants
//   SHAPE = (4, 8, 8, 4), I_CH=32, O_CH=128, BATCH=64, RANK=32
//   core0: (32, 64, 1, 4, 32)   strides (floats): i 8192, b 128, m 32, j 1
//   core1: (32, 64, 32, 8, 32)  strides: i 524288, b 8192, k 256, m 32, j 1
//   core2: same as core1
//   core3: (32, 64, 32, 4, 1)   strides: i 8192, b 128, k 4, m 1
//   weight:(32, 24, 128)        strides: i 3072, row 128, o 1
// ---------------------------------------------------------------------------

static const size_t Y0_OFF = 0;
static const size_t Y1_OFF = 1048576;
static const size_t Y2_OFF = 1048576 + 67108864ull;
static const size_t Y3_OFF = 1048576 + 2ull * 67108864ull;

// ---------------------------------------------------------------------------
// y0: out0[o,b,m,j] = sum_i W[i, m, o] * core0[i,b,0,m,j]
// ---------------------------------------------------------------------------
__global__ void __launch_bounds__(256) y0_kernel(
    const float* __restrict__ core0, const float* __restrict__ weight,
    float* __restrict__ out)
{
    __shared__ float cs[32 * 32];     // [i][j]
    __shared__ float Ws[32 * 128];    // [i][o]
    const int bm = blockIdx.x;
    const int b = bm >> 2;
    const int m = bm & 3;
    const int tid = threadIdx.x;

    {
        int i = tid >> 3, j4 = tid & 7;
        float4 v = *reinterpret_cast<const float4*>(
            core0 + (size_t)i * 8192 + b * 128 + m * 32 + j4 * 4);
        *reinterpret_cast<float4*>(&cs[i * 32 + j4 * 4]) = v;
    }
    #pragma unroll
    for (int q = 0; q < 4; ++q) {
        int idx = tid + 256 * q;
        int i = idx >> 5, o4 = idx & 31;
        float4 v = *reinterpret_cast<const float4*>(
            weight + (size_t)i * 3072 + m * 128 + o4 * 4);
        *reinterpret_cast<float4*>(&Ws[i * 128 + o4 * 4]) = v;
    }
    __syncthreads();

    const int j = tid & 31;
    const int obase = (tid >> 5) * 16;
    float acc[16];
    #pragma unroll
    for (int t = 0; t < 16; ++t) acc[t] = 0.f;
    #pragma unroll 4
    for (int i = 0; i < 32; ++i) {
        float v = cs[i * 32 + j];
        #pragma unroll
        for (int oo = 0; oo < 16; ++oo)
            acc[oo] = fmaf(Ws[i * 128 + obase + oo], v, acc[oo]);
    }
    #pragma unroll
    for (int oo = 0; oo < 16; ++oo)
        out[(size_t)(obase + oo) * 8192 + b * 128 + m * 32 + j] = acc[oo];
}

// ---------------------------------------------------------------------------
// y3: out3[o,b,k,m] = sum_i W[i, 20+m, o] * core3[i,b,k,m]
// ---------------------------------------------------------------------------
__global__ void __launch_bounds__(256) y3_kernel(
    const float* __restrict__ core3, const float* __restrict__ weight,
    float* __restrict__ out)
{
    __shared__ float cs[32 * 128];    // [i][km]
    __shared__ float Ws[32 * 32 * 4]; // [i][o_local][mm]
    const int b = blockIdx.x & 63;
    const int oq = blockIdx.x >> 6;
    const int tid = threadIdx.x;

    #pragma unroll
    for (int q = 0; q < 4; ++q) {
        int idx = tid + 256 * q;
        int i = idx >> 5, km4 = idx & 31;
        float4 v = *reinterpret_cast<const float4*>(
            core3 + (size_t)i * 8192 + b * 128 + km4 * 4);
        *reinterpret_cast<float4*>(&cs[i * 128 + km4 * 4]) = v;
    }
    #pragma unroll
    for (int q = 0; q < 16; ++q) {
        int idx = tid + 256 * q;
        int i = idx >> 7;
        int rem = idx & 127;
        int mm = rem >> 5;
        int ol = rem & 31;
        Ws[(i * 32 + ol) * 4 + mm] =
            weight[(size_t)i * 3072 + (20 + mm) * 128 + oq * 32 + ol];
    }
    __syncthreads();

    const int km = tid & 127;
    const int oh = tid >> 7;
    const int mm = km & 3;
    float acc[16];
    #pragma unroll
    for (int t = 0; t < 16; ++t) acc[t] = 0.f;
    #pragma unroll 4
    for (int i = 0; i < 32; ++i) {
        float v = cs[i * 128 + km];
        #pragma unroll
        for (int oo = 0; oo < 16; ++oo)
            acc[oo] = fmaf(Ws[(i * 32 + oh * 16 + oo) * 4 + mm], v, acc[oo]);
    }
    #pragma unroll
    for (int oo = 0; oo < 16; ++oo) {
        int o = oq * 32 + oh * 16 + oo;
        out[((size_t)o * 64 + b) * 128 + km] = acc[oo];
    }
}

// ---------------------------------------------------------------------------
// cp.async helpers
// ---------------------------------------------------------------------------
__device__ __forceinline__ void cp_async16(float* smem_dst, const float* gmem_src)
{
    uint32_t s = (uint32_t)__cvta_generic_to_shared(smem_dst);
    asm volatile("cp.async.cg.shared.global [%0], [%1], 16;\n"
                 :: "r"(s), "l"(gmem_src) : "memory");
}
__device__ __forceinline__ void cp_async_commit()
{
    asm volatile("cp.async.commit_group;\n" ::: "memory");
}
template<int N>
__device__ __forceinline__ void cp_async_wait()
{
    asm volatile("cp.async.wait_group %0;\n" :: "n"(N) : "memory");
}

// ---------------------------------------------------------------------------
// Fused cores 1 & 2 (single launch, z = core)  —  R12 structure + R15 fix:
//   A[o,k,j] = sum_i 0.5*W[i,off+m,o] * (c[i,b,j,m,k] - c[i,b,k,m,j])   (skew)
//   Q = (I-A)^{-1}(I+A) = 2*(I-A)^{-1} - I
// R15: DIAGONAL pair->thread mapping. Warp w handles wrap-diagonal d=w+1:
//   lane l -> ordered pair (pk=l, pj=(l+d)&31). Consume read banks become
//   (5l+4d)%32 and (5l+d)%32 — both conflict-free (5 odd), vs 4-way before.
//   Antisymmetry V(y,x) = -V(x,y) makes wrapped pairs land bit-identically;
//   d=16 duplicates are exact FP negations, duplicate writers masked.
//   All 512 threads now active in phase 1.
// Phase 1: cp.async 4-buffer / 3-ahead pipeline over 8 chunks of 4 i.
// Phase 2: per-warp blocked register Gauss-Jordan (panel width 8), as R8.
// Epilogue: XOR-swizzled Qstage + coalesced STG.128.
// Amat aliases the phase-1 staging buffers (never simultaneously live).
// __launch_bounds__(512,2): 64-reg budget, no spills, 2 CTAs/SM.
// No pivoting needed: sym(I-A)=I  =>  every pivot >= 1.
// ---------------------------------------------------------------------------
__global__ void __launch_bounds__(512, 2) cayley_kernel(
    const float* __restrict__ core1,
    const float* __restrict__ core2,
    const float* __restrict__ weight,
    float* __restrict__ out)
{
    const int og = blockIdx.x;            // 0..7   (o-group of 16)
    const int bm = blockIdx.y;            // 0..511
    const int b  = bm >> 3;
    const int m  = bm & 7;
    const int c  = blockIdx.z;            // 0..1
    const float* core = c ? core2 : core1;
    float* yout = out + (c ? Y2_OFF : Y1_OFF);
    const int woff = 4 + 8 * c;

    extern __shared__ float smem[];
    // Era 1 (phase 1): raw = smem[0 .. 18432)  = 4 buffers x [4][32][36]
    // Era 2 (phase 2): Amat = smem[0 .. 16896) = [16][32][33]  (aliases raw)
    // Era 3 (epilogue): Qstage = smem[0 .. 16384) = [16][32][32] XOR-swizzled
    // Always: Ws = smem[18432 .. 18944)
    float* raw  = smem;
    float* Amat = smem;
    float* Ws   = smem + 18432;

    const int tid = threadIdx.x;

    {   // 0.5*W slice
        int i  = tid >> 4;
        int oo = tid & 15;
        Ws[i * 16 + oo] =
            0.5f * weight[(size_t)i * 3072 + (woff + m) * 128 + og * 16 + oo];
    }

    // R15 diagonal mapping: warp w -> wrap-diagonal d=w+1; lane l -> (pk,pj)
    const int dly  = (tid >> 5) + 1;      // 1..16
    const int pk   = tid & 31;
    const int pjw  = (pk + dly) & 31;
    const bool writer = (dly < 16) || (pk < 16);   // mask d=16 duplicates

    float acc[16];
    #pragma unroll
    for (int oo = 0; oo < 16; ++oo) acc[oo] = 0.f;

    const float* cbase = core + (size_t)b * 8192 + m * 32;

    // per-thread cp.async slot (2 float4 per thread per chunk)
    const int il0 = tid >> 8;             // 0..1
    const int k0  = (tid >> 3) & 31;      // 0..31
    const int j40 = tid & 7;              // 0..7
    const int il1 = il0 + 2;              // 2..3
    const int d0  = (il0 * 32 + k0) * 36 + j40 * 4;
    const int d1  = (il1 * 32 + k0) * 36 + j40 * 4;
    const size_t g0 = (size_t)il0 * 524288 + k0 * 256 + j40 * 4;
    const size_t g1 = (size_t)il1 * 524288 + k0 * 256 + j40 * 4;

    // --- phase 1: 4-buffer cp.async pipeline, 8 chunks of 4 i --------------
    #pragma unroll
    for (int pre = 0; pre < 3; ++pre) {   // prologue: chunks 0,1,2 in flight
        float* dbuf = raw + pre * 4608;
        const float* src = cbase + (size_t)pre * 4 * 524288;
        cp_async16(dbuf + d0, src + g0);
        cp_async16(dbuf + d1, src + g1);
        cp_async_commit();
    }

    #pragma unroll 1
    for (int ch = 0; ch < 8; ++ch) {
        // wait for chunk ch (keep up to min(2, 7-ch) newer groups in flight)
        if      (ch < 6)  cp_async_wait<2>();
        else if (ch == 6) cp_async_wait<1>();
        else              cp_async_wait<0>();
        __syncthreads();                  // chunk ch visible; ch-1 reads done

        if (ch < 5) {                     // issue chunk ch+3 into buffer of ch-1
            float* dbuf = raw + ((ch + 3) & 3) * 4608;
            const float* src = cbase + (size_t)(ch + 3) * 4 * 524288;
            cp_async16(dbuf + d0, src + g0);
            cp_async16(dbuf + d1, src + g1);
            cp_async_commit();
        }

        {   // all 512 threads: conflict-free dval reads (diagonal mapping)
            const float* rb = raw + (ch & 3) * 4608;
            #pragma unroll
            for (int il = 0; il < 4; ++il) {
                float dval = rb[(il * 32 + pjw) * 36 + pk]
                           - rb[(il * 32 + pk) * 36 + pjw];
                const float4* wrow4 = reinterpret_cast<const float4*>(
                    &Ws[(ch * 4 + il) * 16]);
                float4 w0 = wrow4[0];
                float4 w1 = wrow4[1];
                float4 w2 = wrow4[2];
                float4 w3 = wrow4[3];
                acc[ 0] = fmaf(w0.x, dval, acc[ 0]);
                acc[ 1] = fmaf(w0.y, dval, acc[ 1]);
                acc[ 2] = fmaf(w0.z, dval, acc[ 2]);
                acc[ 3] = fmaf(w0.w, dval, acc[ 3]);
                acc[ 4] = fmaf(w1.x, dval, acc[ 4]);
                acc[ 5] = fmaf(w1.y, dval, acc[ 5]);
                acc[ 6] = fmaf(w1.z, dval, acc[ 6]);
                acc[ 7] = fmaf(w1.w, dval, acc[ 7]);
                acc[ 8] = fmaf(w2.x, dval, acc[ 8]);
                acc[ 9] = fmaf(w2.y, dval, acc[ 9]);
                acc[10] = fmaf(w2.z, dval, acc[10]);
                acc[11] = fmaf(w2.w, dval, acc[11]);
                acc[12] = fmaf(w3.x, dval, acc[12]);
                acc[13] = fmaf(w3.y, dval, acc[13]);
                acc[14] = fmaf(w3.z, dval, acc[14]);
                acc[15] = fmaf(w3.w, dval, acc[15]);
            }
        }
    }
    __syncthreads();                      // last chunk reads done; raw dead

    // --- mirror into smem A matrices (Amat aliases raw) ---------------------
    // Amat[o][pk][pjw] = acc,  Amat[o][pjw][pk] = -acc  (antisymmetric pair)
    if (writer) {
        #pragma unroll
        for (int oo = 0; oo < 16; ++oo) {
            Amat[(oo * 32 + pk) * 33 + pjw] = acc[oo];
            Amat[(oo * 32 + pjw) * 33 + pk] = -acc[oo];
        }
    }
    {   // zero the 16 matrix diagonals: tid -> (o = tid>>5, dd = tid&31)
        int o  = tid >> 5;
        int dd = tid & 31;
        Amat[(o * 32 + dd) * 33 + dd] = 0.f;
    }
    __syncthreads();

    // --- phase 2: per-warp blocked Gauss-Jordan inverse of M = I - A --------
    const int w    = tid >> 5;            // warp -> matrix index
    const int lane = tid & 31;            // lane -> row index

    float M[32];
    #pragma unroll
    for (int q = 0; q < 32; ++q)
        M[q] = (lane == q ? 1.0f : 0.0f) - Amat[(w * 32 + lane) * 33 + q];

    // Warp-private scratch aliased onto this warp's OWN (now dead) Amat rows:
    float* Sw = Amat + w * 1056;
    __syncwarp();                         // M-init loads done before STS alias

    #pragma unroll
    for (int P = 0; P < 4; ++P) {
        const int base = 8 * P;
        float* buf = Sw + (P & 1) * 288;

        // publish pre-panel rows of the 8 panel lanes (all 32 cols)
        if ((lane >> 3) == P) {
            float* row = buf + (lane & 7) * 36;
            #pragma unroll
            for (int g4 = 0; g4 < 8; ++g4)
                *reinterpret_cast<float4*>(row + g4 * 4) =
                    make_float4(M[g4 * 4 + 0], M[g4 * 4 + 1],
                                M[g4 * 4 + 2], M[g4 * 4 + 3]);
        }

        // mini-GJ restricted to panel columns [base, base+8)
        #pragma unroll
        for (int pp = 0; pp < 8; ++pp) {
            const int p = base + pp;
            float piv = __shfl_sync(0xffffffffu, M[p], p);
            float d   = __fdividef(1.0f, piv);   // pivots >= 1, always safe
            float g   = (lane == p) ? (1.0f - d) : M[p] * d;
            #pragma unroll
            for (int qq = 0; qq < 8; ++qq) {
                if (qq == pp) continue;
                const int q = base + qq;
                float prq = __shfl_sync(0xffffffffu, M[q], p);
                M[q] = fmaf(-g, prq, M[q]);
            }
            M[p] = (lane == p) ? d : -g;
        }
        __syncwarp();                     // publish visible; prev buf reads done

        // rank-8 update of the 24 non-panel columns:
        //   M[r][q] = keep * M[r][q] + sum_t E[r][base+t] * S[t][q]
        const float keep = ((lane >> 3) == P) ? 0.0f : 1.0f;
        #pragma unroll
        for (int g4 = 0; g4 < 8; ++g4) {
            if (g4 == 2 * P || g4 == 2 * P + 1) continue;   // compile-time skip
            M[g4 * 4 + 0] *= keep;
            M[g4 * 4 + 1] *= keep;
            M[g4 * 4 + 2] *= keep;
            M[g4 * 4 + 3] *= keep;
        }
        #pragma unroll
        for (int t = 0; t < 8; ++t) {
            const float h = M[base + t];              // E[lane][base+t]
            const float* srow = buf + t * 36;
            #pragma unroll
            for (int g4 = 0; g4 < 8; ++g4) {
                if (g4 == 2 * P || g4 == 2 * P + 1) continue;
                float4 s = *reinterpret_cast<const float4*>(srow + g4 * 4);
                M[g4 * 4 + 0] = fmaf(h, s.x, M[g4 * 4 + 0]);
                M[g4 * 4 + 1] = fmaf(h, s.y, M[g4 * 4 + 1]);
                M[g4 * 4 + 2] = fmaf(h, s.z, M[g4 * 4 + 2]);
                M[g4 * 4 + 3] = fmaf(h, s.w, M[g4 * 4 + 3]);
            }
        }
    }

    // --- epilogue: Q = 2*Minv - I staged to XOR-swizzled smem, then
    //     coalesced STG.128 (each warp-store touches 4 cache lines) ---------
    __syncthreads();                      // all Sw scratch dead block-wide
    {
        // Qstage[w][lane][g] : stride 32, group swizzle g = q4 ^ (lane&7)
        float* qrow = smem + w * 1024 + lane * 32;
        const int sw = lane & 7;
        #pragma unroll
        for (int q4 = 0; q4 < 8; ++q4) {
            float4 v;
            v.x = 2.f * M[q4 * 4 + 0] - (lane == q4 * 4 + 0 ? 1.f : 0.f);
            v.y = 2.f * M[q4 * 4 + 1] - (lane == q4 * 4 + 1 ? 1.f : 0.f);
            v.z = 2.f * M[q4 * 4 + 2] - (lane == q4 * 4 + 2 ? 1.f : 0.f);
            v.w = 2.f * M[q4 * 4 + 3] - (lane == q4 * 4 + 3 ? 1.f : 0.f);
            *reinterpret_cast<float4*>(qrow + ((q4 ^ sw) << 2)) = v;
        }
    }
    __syncwarp();                         // warp-private region: syncwarp ok
    {
        const int o = og * 16 + w;
        float* obase = yout + ((size_t)o * 64 + b) * 8192 + m * 32;
        const int krow_lo = lane >> 3;    // 0..3
        const int j4      = lane & 7;     // 0..7
        const float* qbase = smem + w * 1024;
        #pragma unroll
        for (int it = 0; it < 8; ++it) {
            const int krow = it * 4 + krow_lo;
            float4 v = *reinterpret_cast<const float4*>(
                qbase + krow * 32 + (((j4 ^ (krow & 7))) << 2));
            *reinterpret_cast<float4*>(obase + krow * 256 + j4 * 4) = v;
        }
    }
}

// ---------------------------------------------------------------------------
extern "C" void kernel_launch(void* const* d_in, const int* in_sizes, int n_in,
                              void* d_out, int out_size)
{
    (void)in_sizes; (void)n_in; (void)out_size;
    const float* core0  = (const float*)d_in[0];
    const float* core1  = (const float*)d_in[1];
    const float* core2  = (const float*)d_in[2];
    const float* core3  = (const float*)d_in[3];
    const float* weight = (const float*)d_in[4];
    float* out = (float*)d_out;

    static const int SMEM_BYTES = 18944 * 4;   // 75776 B
    cudaFuncSetAttribute(cayley_kernel,
                         cudaFuncAttributeMaxDynamicSharedMemorySize,
                         SMEM_BYTES);

    cayley_kernel<<<dim3(8, 512, 2), 512, SMEM_BYTES>>>(
        core1, core2, weight, out);
    y0_kernel<<<256, 256>>>(core0, weight, out + Y0_OFF);
    y3_kernel<<<256, 256>>>(core3, weight, out + Y3_OFF);
}